// round 10
// baseline (speedup 1.0000x reference)
#include <cuda_runtime.h>
#include <cuda_fp16.h>
#include <math.h>

// Problem constants
#define BSZ 8
#define HH 256
#define WW 256
#define C1 64
#define NBR 6

// Scratch: weighted neighbor frames (B, 6, H, W) = 12.6 MB
__device__ float g_weighted[BSZ * NBR * HH * WW];

// ---------------------------------------------------------------------------
// Kernel A: fused conv1(2->64,3x3 in fp16 HFMA2) + ReLU/1x1 (fp32) + sigmoid
// 128 threads as 16x8; 4 px/thread; tile = 64x8.
// Pixel pairs (0,1) and (2,3) packed into __half2 lanes.
// ---------------------------------------------------------------------------
#define TWA 64
#define THA 8

__global__ __launch_bounds__(128) void branch_kernel(
    const float* __restrict__ x,
    const float* __restrict__ W1,
    const float* __restrict__ b1,
    const float* __restrict__ W2,
    const float* __restrict__ b2)
{
    __shared__ float sB[THA + 2][TWA + 4];   // 10 x 68 (272B rows, 16B-aligned)
    __shared__ float sC[THA + 2][TWA + 4];
    // Per-channel packed weights (u32 words), stride 20 words = 80B (16B-aligned):
    // [0..8]  = wb as dup half2
    // [9..17] = wc as dup half2
    // [18]    = bias as dup half2
    // [19]    = w2 (1x1 weight) as fp32 bits
    __shared__ unsigned int sWq[C1][20];

    const int bz  = blockIdx.z;
    const int b   = bz / NBR;
    const int n   = bz % NBR;
    const int ty0 = blockIdx.y * THA;
    const int tx0 = blockIdx.x * TWA;
    const int tid = threadIdx.x;
    const int lane = tid & 31;
    const int wrp  = tid >> 5;

    const int checkCh = (n < 3) ? n : (n + 1);
    const int bi = (n < 3) ? 0 : 1;   // pair channel that holds base

    const float* __restrict__ base = x + (size_t)(b * 7 + 3) * (HH * WW);
    const float* __restrict__ chk  = x + (size_t)(b * 7 + checkCh) * (HH * WW);

    // Stage packed weights (convert to dup-half2 once)
    for (int i = tid; i < C1 * 9; i += 128) {
        int c = i / 9, k = i - c * 9;
        float wb = W1[((n * C1 + c) * 2 + bi) * 9 + k];
        float wc = W1[((n * C1 + c) * 2 + (1 - bi)) * 9 + k];
        __half2 wbh = __float2half2_rn(wb);
        __half2 wch = __float2half2_rn(wc);
        sWq[c][k]     = *reinterpret_cast<unsigned int*>(&wbh);
        sWq[c][9 + k] = *reinterpret_cast<unsigned int*>(&wch);
    }
    if (tid < C1) {
        __half2 bh = __float2half2_rn(b1[n * C1 + tid]);
        sWq[tid][18] = *reinterpret_cast<unsigned int*>(&bh);
        sWq[tid][19] = __float_as_uint(W2[n * C1 + tid]);
    }

    // Stage input tiles (warp-stripe: warp -> rows, lane -> cols)
    const bool interior = (ty0 > 0) && (ty0 + THA < HH) && (tx0 > 0) && (tx0 + TWA < WW);
    if (interior) {
        for (int r = wrp; r < THA + 2; r += 4) {
            const float* pb = base + (ty0 + r - 1) * WW + (tx0 - 1);
            const float* pc = chk  + (ty0 + r - 1) * WW + (tx0 - 1);
            sB[r][lane]      = pb[lane];
            sB[r][32 + lane] = pb[32 + lane];
            sC[r][lane]      = pc[lane];
            sC[r][32 + lane] = pc[32 + lane];
            if (lane < 2) {
                sB[r][64 + lane] = pb[64 + lane];
                sC[r][64 + lane] = pc[64 + lane];
            }
        }
    } else {
        for (int r = wrp; r < THA + 2; r += 4) {
            const int gy = ty0 + r - 1;
            const bool okY = (gy >= 0) && (gy < HH);
            const float* pb = base + gy * WW;
            const float* pc = chk  + gy * WW;
#pragma unroll
            for (int s = 0; s < 3; s++) {
                int cc = lane + 32 * s;
                if (cc < TWA + 2) {
                    int gx = tx0 + cc - 1;
                    bool ok = okY && (gx >= 0) && (gx < WW);
                    sB[r][cc] = ok ? pb[gx] : 0.0f;
                    sC[r][cc] = ok ? pc[gx] : 0.0f;
                }
            }
        }
    }
    __syncthreads();

    const int lx = tid & 15;
    const int ly = tid >> 4;
    const int px = lx * 4;

    // fp32 taps -> overlapping half2 pairs: tb2[r][j] = (t[j], t[j+1]), j=0..4.
    // Pixel pair (0,1) at kernel col k uses [k]; pair (2,3) uses [k+2].
    __half2 tb2[3][5], tc2[3][5];
    float c1v, c2v, c3v, c4v;       // fp32 center taps for the gate multiply
#pragma unroll
    for (int r = 0; r < 3; r++) {
        const float* rb = &sB[ly + r][px];
        const float* rc = &sC[ly + r][px];
        float4 b4 = *reinterpret_cast<const float4*>(rb);
        float2 b2v = *reinterpret_cast<const float2*>(rb + 4);
        float4 c4 = *reinterpret_cast<const float4*>(rc);
        float2 c2 = *reinterpret_cast<const float2*>(rc + 4);
        const float tb[6] = {b4.x, b4.y, b4.z, b4.w, b2v.x, b2v.y};
        const float tc[6] = {c4.x, c4.y, c4.z, c4.w, c2.x, c2.y};
#pragma unroll
        for (int j = 0; j < 5; j++) {
            tb2[r][j] = __floats2half2_rn(tb[j], tb[j + 1]);   // one F2FP each
            tc2[r][j] = __floats2half2_rn(tc[j], tc[j + 1]);
        }
        if (r == 1) { c1v = tc[1]; c2v = tc[2]; c3v = tc[3]; c4v = tc[4]; }
    }

    float s0 = 0.f, s1 = 0.f, s2 = 0.f, s3 = 0.f;
    const __half2 hzero = __float2half2_rn(0.0f);

#define H2(u) (*reinterpret_cast<const __half2*>(&(u)))
// One conv tap (base WB + check WC), row R, col K, both pixel pairs
#define HSTEP(WB, WC, R, K)                                   \
    a01 = __hfma2(H2(WB), tb2[R][K],     a01);                \
    a01 = __hfma2(H2(WC), tc2[R][K],     a01);                \
    a23 = __hfma2(H2(WB), tb2[R][K + 2], a23);                \
    a23 = __hfma2(H2(WC), tc2[R][K + 2], a23);

#pragma unroll 2
    for (int c = 0; c < C1; c++) {
        const uint4 q0 = *reinterpret_cast<const uint4*>(&sWq[c][0]);
        const uint4 q1 = *reinterpret_cast<const uint4*>(&sWq[c][4]);
        const uint4 q2 = *reinterpret_cast<const uint4*>(&sWq[c][8]);
        const uint4 q3 = *reinterpret_cast<const uint4*>(&sWq[c][12]);
        const uint4 q4 = *reinterpret_cast<const uint4*>(&sWq[c][16]);
        // wb(k0..8) = q0.x q0.y q0.z q0.w q1.x q1.y q1.z q1.w q2.x
        // wc(k0..8) = q2.y q2.z q2.w q3.x q3.y q3.z q3.w q4.x q4.y
        // bias h2   = q4.z ; w2 fp32 = q4.w

        __half2 a01 = H2(q4.z);
        __half2 a23 = a01;

        HSTEP(q0.x, q2.y, 0, 0)
        HSTEP(q0.y, q2.z, 0, 1)
        HSTEP(q0.z, q2.w, 0, 2)
        HSTEP(q0.w, q3.x, 1, 0)
        HSTEP(q1.x, q3.y, 1, 1)
        HSTEP(q1.y, q3.z, 1, 2)
        HSTEP(q1.z, q3.w, 2, 0)
        HSTEP(q1.w, q4.x, 2, 1)
        HSTEP(q2.x, q4.y, 2, 2)

        // ReLU in fp16 (packed), then fp32 1x1 reduce
        a01 = __hmax2(a01, hzero);
        a23 = __hmax2(a23, hzero);
        const float2 f01 = __half22float2(a01);
        const float2 f23 = __half22float2(a23);
        const float w2f = __uint_as_float(q4.w);
        s0 = fmaf(w2f, f01.x, s0);
        s1 = fmaf(w2f, f01.y, s1);
        s2 = fmaf(w2f, f23.x, s2);
        s3 = fmaf(w2f, f23.y, s3);
    }
#undef HSTEP
#undef H2

    const float bb2 = b2[n];
    const float g0 = 1.f / (1.f + __expf(-(s0 + bb2)));
    const float g1 = 1.f / (1.f + __expf(-(s1 + bb2)));
    const float g2 = 1.f / (1.f + __expf(-(s2 + bb2)));
    const float g3 = 1.f / (1.f + __expf(-(s3 + bb2)));

    const int gy = ty0 + ly;
    float* o = g_weighted + ((size_t)(b * NBR + n) * HH + gy) * WW + tx0 + px;
    float4 w4;
    w4.x = g0 * c1v;
    w4.y = g1 * c2v;
    w4.z = g2 * c3v;
    w4.w = g3 * c4v;
    *reinterpret_cast<float4*>(o) = w4;
}

// ---------------------------------------------------------------------------
// Kernel B: final 7->7 3x3 conv. 128 threads (16x8), 4 px/thread, 64x8 tile.
// (unchanged from round 9 — measured 26.8 us)
// ---------------------------------------------------------------------------
#define TWB 64
#define THB 8

__global__ __launch_bounds__(128) void merge_kernel(
    const float* __restrict__ x,
    const float* __restrict__ Wm,
    const float* __restrict__ bm,
    float* __restrict__ out)
{
    __shared__ float sIn[7][THB + 2][TWB + 4];   // 7 x 10 x 68 (19 KB)
    __shared__ float sW[7][7][12];               // 9 weights padded to 12
    __shared__ float sbm[7];

    const int b   = blockIdx.z;
    const int ty0 = blockIdx.y * THB;
    const int tx0 = blockIdx.x * TWB;
    const int tid = threadIdx.x;
    const int lane = tid & 31;
    const int wrp  = tid >> 5;

    for (int i = tid; i < 7 * 7 * 9; i += 128) {
        int pair = i / 9, k = i - pair * 9;
        sW[pair / 7][pair % 7][k] = Wm[i];
    }
    if (tid < 7) sbm[tid] = bm[tid];

    const bool interior = (ty0 > 0) && (ty0 + THB < HH) && (tx0 > 0) && (tx0 + TWB < WW);
    const float* __restrict__ xc = x + (size_t)(b * 7 + 3) * (HH * WW);
    const float* __restrict__ gw = g_weighted + (size_t)(b * NBR) * (HH * WW);

    if (interior) {
#pragma unroll 1
        for (int p = wrp; p < 70; p += 4) {
            const int ch = p / 10;
            const int r  = p - ch * 10;
            const float* src;
            if (ch == 3) src = xc;
            else {
                int m = (ch < 3) ? ch : (ch - 1);
                src = gw + (size_t)m * (HH * WW);
            }
            const float* row = src + (ty0 + r - 1) * WW + (tx0 - 1);
            sIn[ch][r][lane]      = row[lane];
            sIn[ch][r][32 + lane] = row[32 + lane];
            if (lane < 2) sIn[ch][r][64 + lane] = row[64 + lane];
        }
    } else {
#pragma unroll 1
        for (int p = wrp; p < 70; p += 4) {
            const int ch = p / 10;
            const int r  = p - ch * 10;
            const float* src;
            if (ch == 3) src = xc;
            else {
                int m = (ch < 3) ? ch : (ch - 1);
                src = gw + (size_t)m * (HH * WW);
            }
            const int gy = ty0 + r - 1;
            const bool okY = (gy >= 0) && (gy < HH);
#pragma unroll
            for (int s = 0; s < 3; s++) {
                const int cc = lane + 32 * s;
                if (cc < TWB + 2) {
                    const int gx = tx0 + cc - 1;
                    float v = 0.f;
                    if (okY && gx >= 0 && gx < WW) v = src[gy * WW + gx];
                    sIn[ch][r][cc] = v;
                }
            }
        }
    }
    __syncthreads();

    const int lx = tid & 15;
    const int ly = tid >> 4;
    const int px = lx * 4;

    float acc[7][4];
#pragma unroll
    for (int co = 0; co < 7; co++) {
        const float bv = sbm[co];
        acc[co][0] = bv; acc[co][1] = bv; acc[co][2] = bv; acc[co][3] = bv;
    }

#pragma unroll
    for (int ci = 0; ci < 7; ci++) {
        float t[3][6];
#pragma unroll
        for (int r = 0; r < 3; r++) {
            const float* rp = &sIn[ci][ly + r][px];
            float4 v4 = *reinterpret_cast<const float4*>(rp);
            float2 v2 = *reinterpret_cast<const float2*>(rp + 4);
            t[r][0] = v4.x; t[r][1] = v4.y; t[r][2] = v4.z;
            t[r][3] = v4.w; t[r][4] = v2.x; t[r][5] = v2.y;
        }

#pragma unroll
        for (int co = 0; co < 7; co++) {
            const float4 wA = *reinterpret_cast<const float4*>(&sW[co][ci][0]);
            const float4 wB = *reinterpret_cast<const float4*>(&sW[co][ci][4]);
            const float  w8 = sW[co][ci][8];
            float p0 = acc[co][0], p1 = acc[co][1], p2 = acc[co][2], p3 = acc[co][3];
            p0 = fmaf(wA.x, t[0][0], p0); p1 = fmaf(wA.x, t[0][1], p1);
            p2 = fmaf(wA.x, t[0][2], p2); p3 = fmaf(wA.x, t[0][3], p3);
            p0 = fmaf(wA.y, t[0][1], p0); p1 = fmaf(wA.y, t[0][2], p1);
            p2 = fmaf(wA.y, t[0][3], p2); p3 = fmaf(wA.y, t[0][4], p3);
            p0 = fmaf(wA.z, t[0][2], p0); p1 = fmaf(wA.z, t[0][3], p1);
            p2 = fmaf(wA.z, t[0][4], p2); p3 = fmaf(wA.z, t[0][5], p3);
            p0 = fmaf(wA.w, t[1][0], p0); p1 = fmaf(wA.w, t[1][1], p1);
            p2 = fmaf(wA.w, t[1][2], p2); p3 = fmaf(wA.w, t[1][3], p3);
            p0 = fmaf(wB.x, t[1][1], p0); p1 = fmaf(wB.x, t[1][2], p1);
            p2 = fmaf(wB.x, t[1][3], p2); p3 = fmaf(wB.x, t[1][4], p3);
            p0 = fmaf(wB.y, t[1][2], p0); p1 = fmaf(wB.y, t[1][3], p1);
            p2 = fmaf(wB.y, t[1][4], p2); p3 = fmaf(wB.y, t[1][5], p3);
            p0 = fmaf(wB.z, t[2][0], p0); p1 = fmaf(wB.z, t[2][1], p1);
            p2 = fmaf(wB.z, t[2][2], p2); p3 = fmaf(wB.z, t[2][3], p3);
            p0 = fmaf(wB.w, t[2][1], p0); p1 = fmaf(wB.w, t[2][2], p1);
            p2 = fmaf(wB.w, t[2][3], p2); p3 = fmaf(wB.w, t[2][4], p3);
            p0 = fmaf(w8,   t[2][2], p0); p1 = fmaf(w8,   t[2][3], p1);
            p2 = fmaf(w8,   t[2][4], p2); p3 = fmaf(w8,   t[2][5], p3);
            acc[co][0] = p0; acc[co][1] = p1; acc[co][2] = p2; acc[co][3] = p3;
        }
    }

    const int gy = ty0 + ly;
#pragma unroll
    for (int co = 0; co < 7; co++) {
        float* o = out + ((size_t)(b * 7 + co) * HH + gy) * WW + tx0 + px;
        float4 v4;
        v4.x = acc[co][0]; v4.y = acc[co][1]; v4.z = acc[co][2]; v4.w = acc[co][3];
        *reinterpret_cast<float4*>(o) = v4;
    }
}

// ---------------------------------------------------------------------------
extern "C" void kernel_launch(void* const* d_in, const int* in_sizes, int n_in,
                              void* d_out, int out_size)
{
    const float* x  = (const float*)d_in[0];   // (8, 7, 256, 256)
    const float* W1 = (const float*)d_in[1];   // (6, 64, 2, 3, 3)
    const float* b1 = (const float*)d_in[2];   // (6, 64)
    const float* W2 = (const float*)d_in[3];   // (6, 1, 64, 1, 1)
    const float* b2 = (const float*)d_in[4];   // (6, 1)
    const float* Wm = (const float*)d_in[5];   // (7, 7, 3, 3)
    const float* bm = (const float*)d_in[6];   // (7,)

    dim3 grid1(WW / TWA, HH / THA, BSZ * NBR);   // 4 x 32 x 48 = 6144
    branch_kernel<<<grid1, 128>>>(x, W1, b1, W2, b2);

    dim3 grid2(WW / TWB, HH / THB, BSZ);         // 4 x 32 x 8 = 1024
    merge_kernel<<<grid2, 128>>>(x, Wm, bm, (float*)d_out);
}